// round 1
// baseline (speedup 1.0000x reference)
#include <cuda_runtime.h>
#include <math.h>

#define Bsz   1024
#define TENC  64
#define FDIM  121
#define Hdim  512
#define SEG   32
#define FOURH 2048
#define BH    (Bsz * Hdim)          // 524288 floats per (t) slot

// ---------------------------------------------------------------------------
// Scratch (static device globals; no runtime allocation)
// ---------------------------------------------------------------------------
__device__ float g_pre[(size_t)TENC * Bsz * FOURH];                 // 512 MB, reused 3x
__device__ float g_chain0[(size_t)(TENC + SEG + 1) * Bsz * Hdim];   // layer-0 h chain (enc then dec)
__device__ float g_chain1[(size_t)(TENC + SEG + 1) * Bsz * Hdim];   // layer-1 h chain
__device__ float g_c0[(size_t)Bsz * Hdim];
__device__ float g_c1[(size_t)Bsz * Hdim];

// ---------------------------------------------------------------------------
// Batched input-projection SGEMM: C[M,2048] = A[M,K] @ Bw[K,2048]
// Optional output row permutation: out_row = (m % Tcount)*(M/Tcount) + m/Tcount
// (converts b-major x rows into [t][b]-major pre layout).
// Tile 128x128, Kc=16, 256 threads, 8x8 per-thread.
// ---------------------------------------------------------------------------
__global__ void __launch_bounds__(256) sgemm_pre_kernel(
    const float* __restrict__ A, const float* __restrict__ Bw,
    float* __restrict__ C, int M, int K, int Tcount)
{
    __shared__ float As[16][132];
    __shared__ float Bs[16][128];
    const int t  = threadIdx.x;
    const int tr = t >> 4, tc = t & 15;
    const int rowBase = blockIdx.y * 128;
    const int colBase = blockIdx.x * 128;

    float acc[8][8];
#pragma unroll
    for (int i = 0; i < 8; i++)
#pragma unroll
        for (int j = 0; j < 8; j++) acc[i][j] = 0.f;

    for (int k0 = 0; k0 < K; k0 += 16) {
#pragma unroll
        for (int i = 0; i < 8; i++) {
            int idx = t + i * 256;           // 0..2047
            int row = idx >> 4;              // 0..127
            int kk  = idx & 15;
            float v = 0.f;
            if (k0 + kk < K) v = A[(size_t)(rowBase + row) * K + k0 + kk];
            As[kk][row] = v;
        }
#pragma unroll
        for (int i = 0; i < 8; i++) {
            int idx = t + i * 256;
            int kk  = idx >> 7;              // 0..15
            int cc  = idx & 127;
            float v = 0.f;
            if (k0 + kk < K) v = Bw[(size_t)(k0 + kk) * FOURH + colBase + cc];
            Bs[kk][cc] = v;
        }
        __syncthreads();
#pragma unroll
        for (int k = 0; k < 16; k++) {
            float4 a0 = *reinterpret_cast<const float4*>(&As[k][tr * 4]);
            float4 a1 = *reinterpret_cast<const float4*>(&As[k][64 + tr * 4]);
            float4 b0 = *reinterpret_cast<const float4*>(&Bs[k][tc * 4]);
            float4 b1 = *reinterpret_cast<const float4*>(&Bs[k][64 + tc * 4]);
            float av[8] = {a0.x, a0.y, a0.z, a0.w, a1.x, a1.y, a1.z, a1.w};
            float bv[8] = {b0.x, b0.y, b0.z, b0.w, b1.x, b1.y, b1.z, b1.w};
#pragma unroll
            for (int r = 0; r < 8; r++)
#pragma unroll
                for (int j = 0; j < 8; j++) acc[r][j] += av[r] * bv[j];
        }
        __syncthreads();
    }

#pragma unroll
    for (int r = 0; r < 8; r++) {
        int lrow = (r < 4) ? (tr * 4 + r) : (64 + tr * 4 + (r - 4));
        int m = rowBase + lrow;
        int orow = m;
        if (Tcount > 1) {
            int tt = m % Tcount;
            int bb = m / Tcount;
            orow = tt * (M / Tcount) + bb;
        }
        float* crow = C + (size_t)orow * FOURH + colBase;
#pragma unroll
        for (int j = 0; j < 8; j++) {
            int col = (j < 4) ? (tc * 4 + j) : (64 + tc * 4 + (j - 4));
            crow[col] = acc[r][j];
        }
    }
}

// ---------------------------------------------------------------------------
// Fused recurrent LSTM step:
//   z[b, g*512+hc] = pre[b, g*512+hc] + sum_k h_prev[b,k]*U[k, g*512+hc]
//                    + bias[..] (+ dec_in[b]*dW0[..])
//   gates i,f,g,o -> c,h update, written in the GEMM epilogue.
// Tile: 128 rows x 32 hcols (=128 z cols covering 4 gates), 256 threads,
// per-thread 8 rows x (4 gates x 2 hcols). Grid (8, 16).
// ---------------------------------------------------------------------------
__global__ void __launch_bounds__(256) lstm_step_kernel(
    const float* __restrict__ h_prev,   // [B,H]
    const float* __restrict__ pre,      // [B,4H] slice or nullptr
    const float* __restrict__ U,        // [H,4H]
    const float* __restrict__ bias,     // [4H]
    const float* __restrict__ dec,      // &dec_in[t] (stride SEG) or nullptr
    const float* __restrict__ dW0,      // [4H] or nullptr
    float* __restrict__ c_state,        // [B,H] (in place)
    float* __restrict__ h_out)          // [B,H]
{
    __shared__ float As[32][132];
    __shared__ float Bs[32][128];
    const int t  = threadIdx.x;
    const int tr = t >> 4, tc = t & 15;
    const int rowBase = blockIdx.x * 128;
    const int hb = blockIdx.y * 32;

    float acc[8][8];
#pragma unroll
    for (int i = 0; i < 8; i++)
#pragma unroll
        for (int j = 0; j < 8; j++) acc[i][j] = 0.f;

    for (int k0 = 0; k0 < Hdim; k0 += 32) {
        // A: h_prev[rowBase+row][k0+kk] -> As[kk][row]  (float4 along k)
#pragma unroll
        for (int i = 0; i < 4; i++) {
            int linear = t + i * 256;        // float4 id, 0..1023
            int row = linear >> 3;           // 0..127
            int k4  = (linear & 7) * 4;      // 0,4,...,28
            float4 v = *reinterpret_cast<const float4*>(
                &h_prev[(size_t)(rowBase + row) * Hdim + k0 + k4]);
            As[k4 + 0][row] = v.x;
            As[k4 + 1][row] = v.y;
            As[k4 + 2][row] = v.z;
            As[k4 + 3][row] = v.w;
        }
        // B: U[k0+k][g*512 + hb + n] -> Bs[k][g*32+n]
#pragma unroll
        for (int i = 0; i < 4; i++) {
            int linear = t + i * 256;        // float4 id, 0..1023
            int k  = linear >> 5;            // 0..31
            int c  = (linear & 31) * 4;      // 0..124
            int g  = c >> 5;
            int n  = c & 31;
            float4 v = *reinterpret_cast<const float4*>(
                &U[(size_t)(k0 + k) * FOURH + g * 512 + hb + n]);
            *reinterpret_cast<float4*>(&Bs[k][c]) = v;
        }
        __syncthreads();
#pragma unroll
        for (int k = 0; k < 32; k++) {
            float4 a0 = *reinterpret_cast<const float4*>(&As[k][tr * 4]);
            float4 a1 = *reinterpret_cast<const float4*>(&As[k][64 + tr * 4]);
            float av[8] = {a0.x, a0.y, a0.z, a0.w, a1.x, a1.y, a1.z, a1.w};
            float2 b0 = *reinterpret_cast<const float2*>(&Bs[k][0 * 32 + tc * 2]);
            float2 b1 = *reinterpret_cast<const float2*>(&Bs[k][1 * 32 + tc * 2]);
            float2 b2 = *reinterpret_cast<const float2*>(&Bs[k][2 * 32 + tc * 2]);
            float2 b3 = *reinterpret_cast<const float2*>(&Bs[k][3 * 32 + tc * 2]);
            float bv[8] = {b0.x, b0.y, b1.x, b1.y, b2.x, b2.y, b3.x, b3.y};
#pragma unroll
            for (int r = 0; r < 8; r++)
#pragma unroll
                for (int j = 0; j < 8; j++) acc[r][j] += av[r] * bv[j];
        }
        __syncthreads();
    }

    // Epilogue: gates + state update
#pragma unroll
    for (int r = 0; r < 8; r++) {
        int lrow = (r < 4) ? (tr * 4 + r) : (64 + tr * 4 + (r - 4));
        int row = rowBase + lrow;
#pragma unroll
        for (int n = 0; n < 2; n++) {
            int hcol = hb + tc * 2 + n;
            float zi = acc[r][0 * 2 + n] + bias[0 * 512 + hcol];
            float zf = acc[r][1 * 2 + n] + bias[1 * 512 + hcol];
            float zg = acc[r][2 * 2 + n] + bias[2 * 512 + hcol];
            float zo = acc[r][3 * 2 + n] + bias[3 * 512 + hcol];
            if (pre) {
                const float* p = pre + (size_t)row * FOURH + hcol;
                zi += p[0];
                zf += p[512];
                zg += p[1024];
                zo += p[1536];
            }
            if (dec) {
                float dv = dec[(size_t)row * SEG];
                zi += dv * dW0[hcol];
                zf += dv * dW0[512 + hcol];
                zg += dv * dW0[1024 + hcol];
                zo += dv * dW0[1536 + hcol];
            }
            float ig = 1.f / (1.f + expf(-zi));
            float fg = 1.f / (1.f + expf(-zf));
            float gg = tanhf(zg);
            float og = 1.f / (1.f + expf(-zo));
            size_t sidx = (size_t)row * Hdim + hcol;
            float cnew = fg * c_state[sidx] + ig * gg;
            c_state[sidx] = cnew;
            h_out[sidx] = og * tanhf(cnew);
        }
    }
}

// ---------------------------------------------------------------------------
// Final Dense(1): out[b, s] = dot(d1[s][b,:], denseW) + denseb
// One warp per output.
// ---------------------------------------------------------------------------
__global__ void __launch_bounds__(256) dense_kernel(
    const float* __restrict__ chain1, const float* __restrict__ W,
    const float* __restrict__ bb, float* __restrict__ out)
{
    int wid  = (blockIdx.x * blockDim.x + threadIdx.x) >> 5;
    int lane = threadIdx.x & 31;
    if (wid >= Bsz * SEG) return;
    int b = wid / SEG, s = wid % SEG;
    const float* hptr = chain1 + (size_t)(TENC + 1 + s) * BH + (size_t)b * Hdim;
    float sum = 0.f;
#pragma unroll 4
    for (int k = lane; k < Hdim; k += 32) sum += hptr[k] * W[k];
#pragma unroll
    for (int o = 16; o > 0; o >>= 1) sum += __shfl_down_sync(0xffffffffu, sum, o);
    if (lane == 0) out[(size_t)b * SEG + s] = sum + bb[0];
}

// ---------------------------------------------------------------------------
// Host launch (graph-capturable: kernels + async memsets only)
// ---------------------------------------------------------------------------
extern "C" void kernel_launch(void* const* d_in, const int* in_sizes, int n_in,
                              void* d_out, int out_size)
{
    const float* x      = (const float*)d_in[0];
    const float* decin  = (const float*)d_in[1];
    const float* eW0    = (const float*)d_in[2];
    const float* eU0    = (const float*)d_in[3];
    const float* eb0    = (const float*)d_in[4];
    const float* eW1    = (const float*)d_in[5];
    const float* eU1    = (const float*)d_in[6];
    const float* eb1    = (const float*)d_in[7];
    const float* dW0    = (const float*)d_in[8];
    const float* dU0    = (const float*)d_in[9];
    const float* db0    = (const float*)d_in[10];
    const float* dW1    = (const float*)d_in[11];
    const float* dU1    = (const float*)d_in[12];
    const float* db1    = (const float*)d_in[13];
    const float* denseW = (const float*)d_in[14];
    const float* denseb = (const float*)d_in[15];
    float* out = (float*)d_out;

    float *pre, *ch0, *ch1, *c0, *c1;
    cudaGetSymbolAddress((void**)&pre, g_pre);
    cudaGetSymbolAddress((void**)&ch0, g_chain0);
    cudaGetSymbolAddress((void**)&ch1, g_chain1);
    cudaGetSymbolAddress((void**)&c0, g_c0);
    cudaGetSymbolAddress((void**)&c1, g_c1);

    // zero initial h (chain slot 0) and c states
    cudaMemsetAsync(ch0, 0, (size_t)BH * sizeof(float));
    cudaMemsetAsync(ch1, 0, (size_t)BH * sizeof(float));
    cudaMemsetAsync(c0, 0, (size_t)BH * sizeof(float));
    cudaMemsetAsync(c1, 0, (size_t)BH * sizeof(float));

    dim3 gStep(Bsz / 128, Hdim / 32);   // (8, 16)

    // --- encoder layer 0: pre = x @ eW0 (permuted to [t][b]) ---
    sgemm_pre_kernel<<<dim3(FOURH / 128, (Bsz * TENC) / 128), 256>>>(
        x, eW0, pre, Bsz * TENC, FDIM, TENC);
    for (int tt = 0; tt < TENC; tt++)
        lstm_step_kernel<<<gStep, 256>>>(
            ch0 + (size_t)tt * BH, pre + (size_t)tt * Bsz * FOURH,
            eU0, eb0, nullptr, nullptr, c0, ch0 + (size_t)(tt + 1) * BH);

    // --- encoder layer 1: pre = y0 @ eW1 (y0 = chain0 slots 1..64, [t][b]) ---
    sgemm_pre_kernel<<<dim3(FOURH / 128, (Bsz * TENC) / 128), 256>>>(
        ch0 + (size_t)BH, eW1, pre, Bsz * TENC, Hdim, 1);
    for (int tt = 0; tt < TENC; tt++)
        lstm_step_kernel<<<gStep, 256>>>(
            ch1 + (size_t)tt * BH, pre + (size_t)tt * Bsz * FOURH,
            eU1, eb1, nullptr, nullptr, c1, ch1 + (size_t)(tt + 1) * BH);

    // --- decoder layer 0: input is dec_in (zeros per reference, but honored) ---
    // seeds: h = enc L0 final (chain0 slot 64), c = c0 (continues in place)
    for (int tt = 0; tt < SEG; tt++)
        lstm_step_kernel<<<gStep, 256>>>(
            ch0 + (size_t)(TENC + tt) * BH, nullptr,
            dU0, db0, decin + tt, dW0, c0, ch0 + (size_t)(TENC + 1 + tt) * BH);

    // --- decoder layer 1: pre = d0 @ dW1 (d0 = chain0 slots 65..96, [t][b]) ---
    sgemm_pre_kernel<<<dim3(FOURH / 128, (Bsz * SEG) / 128), 256>>>(
        ch0 + (size_t)(TENC + 1) * BH, dW1, pre, Bsz * SEG, Hdim, 1);
    for (int tt = 0; tt < SEG; tt++)
        lstm_step_kernel<<<gStep, 256>>>(
            ch1 + (size_t)(TENC + tt) * BH, pre + (size_t)tt * Bsz * FOURH,
            dU1, db1, nullptr, nullptr, c1, ch1 + (size_t)(TENC + 1 + tt) * BH);

    // --- final dense ---
    dense_kernel<<<(Bsz * SEG * 32) / 256, 256>>>(ch1, denseW, denseb, out);
}

// round 4
// speedup vs baseline: 1.5913x; 1.5913x over previous
#include <cuda_runtime.h>
#include <cuda_bf16.h>
#include <math.h>
#include <stdint.h>

#define Bsz   1024
#define TENC  64
#define SEG   32
#define Hdim  512
#define FOURH 2048
#define BH    (Bsz * Hdim)

// Does this device-compilation pass have tcgen05 (arch-specific 'a' / family 'f')?
#if defined(__CUDA_ARCH__) && (defined(__CUDA_ARCH_FEAT_SM103_ALL) || \
    defined(__CUDA_ARCH_FEAT_SM100_ALL) || defined(__CUDA_ARCH_SPECIFIC__) || \
    defined(__CUDA_ARCH_FAMILY_SPECIFIC__))
#define TC_OK 1
#else
#define TC_OK 0
#endif

// ---------------------------------------------------------------------------
// Static device scratch
// ---------------------------------------------------------------------------
__device__ float g_pre[(size_t)TENC * Bsz * FOURH];              // permuted cols
__device__ __nv_bfloat16 g_h0hi[(size_t)97 * BH];
__device__ __nv_bfloat16 g_h0lo[(size_t)97 * BH];
__device__ __nv_bfloat16 g_h1hi[(size_t)97 * BH];
__device__ __nv_bfloat16 g_h1lo[(size_t)97 * BH];
__device__ float g_c0[BH];
__device__ float g_c1[BH];
__device__ __nv_bfloat16 g_xhi[(size_t)65536 * 128];
__device__ __nv_bfloat16 g_xlo[(size_t)65536 * 128];
__device__ __nv_bfloat16 g_eU0h[(size_t)2048 * 512], g_eU0l[(size_t)2048 * 512];
__device__ __nv_bfloat16 g_eU1h[(size_t)2048 * 512], g_eU1l[(size_t)2048 * 512];
__device__ __nv_bfloat16 g_dU0h[(size_t)2048 * 512], g_dU0l[(size_t)2048 * 512];
__device__ __nv_bfloat16 g_dU1h[(size_t)2048 * 512], g_dU1l[(size_t)2048 * 512];
__device__ __nv_bfloat16 g_eW1h[(size_t)2048 * 512], g_eW1l[(size_t)2048 * 512];
__device__ __nv_bfloat16 g_dW1h[(size_t)2048 * 512], g_dW1l[(size_t)2048 * 512];
__device__ __nv_bfloat16 g_eW0h[(size_t)2048 * 128], g_eW0l[(size_t)2048 * 128];

// ---------------------------------------------------------------------------
// Helpers
// ---------------------------------------------------------------------------
__device__ __forceinline__ uint32_t smem_to_u32(const void* p) {
    uint32_t a;
    asm("{ .reg .u64 t; cvta.to.shared.u64 t, %1; cvt.u32.u64 %0, t; }" : "=r"(a) : "l"(p));
    return a;
}

__device__ __forceinline__ void lstm_gates(float zi, float zf, float zg, float zo,
                                           float cold, float& cn, float& h) {
    float ig = 1.f / (1.f + expf(-zi));
    float fg = 1.f / (1.f + expf(-zf));
    float gg = tanhf(zg);
    float og = 1.f / (1.f + expf(-zo));
    cn = fg * cold + ig * gg;
    h  = og * tanhf(cn);
}

#if TC_OK
__device__ __forceinline__ uint32_t elect_one_pred() {
    uint32_t pred;
    asm volatile(
        "{\n\t.reg .pred p;\n\t"
        "elect.sync _|p, 0xFFFFFFFF;\n\t"
        "selp.b32 %0, 1, 0, p;\n\t}"
        : "=r"(pred));
    return pred;
}

#define TCGEN05_ALLOC(addr, n) \
    asm volatile("tcgen05.alloc.cta_group::1.sync.aligned.shared::cta.b32 [%0], %1;" \
                 :: "r"((uint32_t)(addr)), "r"((uint32_t)(n)) : "memory")
#define TCGEN05_DEALLOC(tm, n) \
    asm volatile("tcgen05.dealloc.cta_group::1.sync.aligned.b32 %0, %1;" :: "r"(tm), "r"((uint32_t)(n)))
#define TCGEN05_RELINQ() \
    asm volatile("tcgen05.relinquish_alloc_permit.cta_group::1.sync.aligned;")
#define TCGEN05_COMMIT(mb) \
    asm volatile("tcgen05.commit.cta_group::1.mbarrier::arrive::one.shared::cluster.b64 [%0];" \
                 :: "r"((uint32_t)(mb)) : "memory")
#define TCGEN05_WAIT_LD() asm volatile("tcgen05.wait::ld.sync.aligned;" ::: "memory")
#define TCGEN05_FENCE_AFTER() asm volatile("tcgen05.fence::after_thread_sync;" ::: "memory")
#define MBARRIER_INIT(mb, cnt) \
    asm volatile("mbarrier.init.shared.b64 [%0], %1;" :: "r"((uint32_t)(mb)), "r"((uint32_t)(cnt)) : "memory")
#define FENCE_PROXY_ASYNC() asm volatile("fence.proxy.async.shared::cta;" ::: "memory")

#define MBARRIER_WAIT_PARITY(mbar_smem_addr, phase_parity) do { \
    uint32_t _mbar = (uint32_t)(mbar_smem_addr); \
    uint32_t _parity = (uint32_t)(phase_parity); \
    uint32_t _done; \
    asm volatile( \
        "{\n\t.reg .pred p;\n\t" \
        "mbarrier.try_wait.parity.acquire.cta.shared::cta.b64 p, [%1], %2;\n\t" \
        "selp.b32 %0, 1, 0, p;\n\t}" \
        : "=r"(_done) : "r"(_mbar), "r"(_parity) : "memory"); \
    if (!_done) { \
        asm volatile( \
            "{\n\t.reg .pred P1;\n\t" \
            "WAIT_LOOP_%=:\n\t" \
            "mbarrier.try_wait.parity.acquire.cta.shared::cta.b64 P1, [%0], %1, 0x989680;\n\t" \
            "@P1 bra.uni WAIT_DONE_%=;\n\t" \
            "bra.uni WAIT_LOOP_%=;\n\t" \
            "WAIT_DONE_%=:\n\t}" \
            :: "r"(_mbar), "r"(_parity) : "memory"); \
    } \
} while (0)

#define TCGEN05_LD_32X32B_X32(r, tmem_addr) \
    asm volatile( \
        "tcgen05.ld.sync.aligned.32x32b.x32.b32 " \
        "{%0, %1, %2, %3, %4, %5, %6, %7, " \
        " %8, %9, %10, %11, %12, %13, %14, %15, " \
        " %16, %17, %18, %19, %20, %21, %22, %23, " \
        " %24, %25, %26, %27, %28, %29, %30, %31}, [%32];" \
        : "=r"((r)[0]),  "=r"((r)[1]),  "=r"((r)[2]),  "=r"((r)[3]), \
          "=r"((r)[4]),  "=r"((r)[5]),  "=r"((r)[6]),  "=r"((r)[7]), \
          "=r"((r)[8]),  "=r"((r)[9]),  "=r"((r)[10]), "=r"((r)[11]), \
          "=r"((r)[12]), "=r"((r)[13]), "=r"((r)[14]), "=r"((r)[15]), \
          "=r"((r)[16]), "=r"((r)[17]), "=r"((r)[18]), "=r"((r)[19]), \
          "=r"((r)[20]), "=r"((r)[21]), "=r"((r)[22]), "=r"((r)[23]), \
          "=r"((r)[24]), "=r"((r)[25]), "=r"((r)[26]), "=r"((r)[27]), \
          "=r"((r)[28]), "=r"((r)[29]), "=r"((r)[30]), "=r"((r)[31]) \
        : "r"(tmem_addr))

static constexpr uint64_t SMEM_DESC_BASE_SW128 =
    (uint64_t(2)  << 61) | (uint64_t(1) << 46) | (uint64_t(64) << 32) | (uint64_t(1) << 16);
#define MAKE_SMEM_DESC(a) (SMEM_DESC_BASE_SW128 | ((uint64_t)((a) >> 4) & 0x3FFF))

// idesc kind::f16: dtype F32, atype/btype BF16, N=128, M=128
#define MMA_IDESC 0x8200490u

__device__ __forceinline__ void mma_f16_ss(uint32_t d, uint64_t a, uint64_t b,
                                           uint32_t idesc, bool acc) {
    uint32_t en = acc ? 1u : 0u;
    asm volatile(
        "{\n\t.reg .pred p;\n\t"
        "setp.ne.u32 p, %5, 0;\n\t"
        "tcgen05.mma.cta_group::1.kind::f16 [%0], %1, %2, %3, {%4, %4, %4, %4}, p;\n\t}"
        :: "r"(d), "l"(a), "l"(b), "r"(idesc), "r"(0u), "r"(en) : "memory");
}
#endif // TC_OK

// ---------------------------------------------------------------------------
// Weight conversion: U[K][2048] fp32 -> B-format [2048 permuted N][Kpad] bf16 hi/lo
// permuted n: hT=n>>7, r=n&127, g=r&3, nl=r>>2, orig = g*512 + hT*32 + nl
// ---------------------------------------------------------------------------
__global__ void __launch_bounds__(256) conv_weight(
    const float* __restrict__ U, __nv_bfloat16* __restrict__ bh,
    __nv_bfloat16* __restrict__ bl, int K, int Kpad)
{
    int idx = blockIdx.x * 256 + threadIdx.x;
    if (idx >= 2048 * Kpad) return;
    int n = idx / Kpad, k = idx % Kpad;
    int r = n & 127, hT = n >> 7;
    int g = r & 3, nl = r >> 2;
    int orig = g * 512 + hT * 32 + nl;
    float v = (k < K) ? U[(size_t)k * FOURH + orig] : 0.f;
    __nv_bfloat16 h = __float2bfloat16(v);
    bh[idx] = h;
    bl[idx] = __float2bfloat16(v - __bfloat162float(h));
}

// x[b][t][121] -> rows m=t*1024+b, [m][128] bf16 hi/lo (zero-padded K)
__global__ void __launch_bounds__(256) conv_x(
    const float* __restrict__ x, __nv_bfloat16* __restrict__ xh, __nv_bfloat16* __restrict__ xl)
{
    size_t idx = (size_t)blockIdx.x * 256 + threadIdx.x;
    if (idx >= (size_t)65536 * 128) return;
    int m = (int)(idx >> 7), k = (int)(idx & 127);
    int t = m >> 10, b = m & 1023;
    float v = (k < 121) ? x[(size_t)b * (TENC * 121) + t * 121 + k] : 0.f;
    __nv_bfloat16 h = __float2bfloat16(v);
    xh[idx] = h;
    xl[idx] = __float2bfloat16(v - __bfloat162float(h));
}

// ---------------------------------------------------------------------------
// GEMM (split-bf16): D = Ahi@Bhi^T + Alo@Bhi^T + Ahi@Blo^T    (TC path)
//                    D = (Ahi+Alo)@(Bhi+Blo)^T                 (fallback path)
// CTA tile 128 rows x 128 permuted cols. mode 0: D -> outC. mode 1: LSTM epi.
// ---------------------------------------------------------------------------
__global__ void __launch_bounds__(128) tc_gemm(
    const __nv_bfloat16* __restrict__ Ahi, const __nv_bfloat16* __restrict__ Alo,
    const __nv_bfloat16* __restrict__ Bhi, const __nv_bfloat16* __restrict__ Blo,
    const float* __restrict__ pre,
    const float* __restrict__ bias,
    const float* __restrict__ dec, const float* __restrict__ dW0,
    float* __restrict__ c_state,
    __nv_bfloat16* __restrict__ ohi, __nv_bfloat16* __restrict__ olo,
    float* __restrict__ outC,
    int kA, int mode)
{
    extern __shared__ char smem[];
    const uint32_t sb = smem_to_u32(smem);
    const uint32_t tb = (sb + 1023u) & ~1023u;
    char* smemc = smem + (tb - sb);

    const int tid = threadIdx.x;
    const int nb = blockIdx.x;
    const size_t rowBase = (size_t)blockIdx.y * 128;

#if TC_OK
    // =================== tcgen05 path ===================
    const uint32_t MB0 = tb + 8;
    const uint32_t MB1 = tb + 16;
    const uint32_t MBF = tb + 24;

    if (tid < 32) {
        TCGEN05_ALLOC(tb, 128);
        TCGEN05_RELINQ();
    }
    if (tid == 0) {
        MBARRIER_INIT(MB0, 1);
        MBARRIER_INIT(MB1, 1);
        MBARRIER_INIT(MBF, 1);
    }
    __syncthreads();
    uint32_t tmem_base;
    asm volatile("ld.shared.b32 %0, [%1];" : "=r"(tmem_base) : "r"(tb));

    const int terms = kA >> 6;
    const int nch = terms * 3;
    int wp0 = 0, wp1 = 0;

    for (int c = 0; c < nch; c++) {
        const int buf = c & 1;
        if (c >= 2) {
            if (buf) { MBARRIER_WAIT_PARITY(MB1, wp1 & 1); wp1++; }
            else     { MBARRIER_WAIT_PARITY(MB0, wp0 & 1); wp0++; }
        }
        const int term = c / terms;
        const int koff = (c % terms) * 64;
        const __nv_bfloat16* As = (term == 1) ? Alo : Ahi;
        const __nv_bfloat16* Bw = (term == 2) ? Blo : Bhi;
        char* ab = smemc + 1024 + buf * 32768;
        char* bb = ab + 16384;
#pragma unroll
        for (int i = 0; i < 8; i++) {
            int idx = i * 128 + tid;
            int r = idx >> 3, s = idx & 7;
            float4 va = *(const float4*)(As + (rowBase + r) * kA + koff + s * 8);
            float4 vb = *(const float4*)(Bw + (size_t)(nb * 128 + r) * kA + koff + s * 8);
            uint32_t off = (uint32_t)(r * 128 + s * 16);
            uint32_t sw = off ^ ((off >> 3) & 0x70);
            *(float4*)(ab + sw) = va;
            *(float4*)(bb + sw) = vb;
        }
        FENCE_PROXY_ASYNC();
        __syncthreads();
        if (tid < 32) {
            if (elect_one_pred()) {
                uint64_t ad = MAKE_SMEM_DESC(tb + 1024 + buf * 32768);
                uint64_t bd = MAKE_SMEM_DESC(tb + 1024 + buf * 32768 + 16384);
#pragma unroll
                for (int j = 0; j < 4; j++)
                    mma_f16_ss(tmem_base, ad + j * 2, bd + j * 2, MMA_IDESC, !(c == 0 && j == 0));
                TCGEN05_COMMIT(buf ? MB1 : MB0);
            }
        }
    }
    if (tid < 32) {
        if (elect_one_pred()) TCGEN05_COMMIT(MBF);
    }
    __syncthreads();
    MBARRIER_WAIT_PARITY(MBF, 0);
    TCGEN05_FENCE_AFTER();

    // ---- epilogue (GEMM smem now free) ----
    float* spre = (float*)(smemc + 1024);                  // 128 x 33 fp32
    float* scf  = (float*)(smemc + 17920);                 // 128 x 33 fp32
    __nv_bfloat16* shi = (__nv_bfloat16*)(smemc + 34816);  // 128 x 34 bf16
    __nv_bfloat16* slo = (__nv_bfloat16*)(smemc + 43520);  // 128 x 34 bf16

    if (mode == 1) {
#pragma unroll 4
        for (int i = 0; i < 32; i++) {
            int idx = i * 128 + tid, r = idx >> 5, cc = idx & 31;
            scf[r * 33 + cc] = c_state[(rowBase + r) * Hdim + nb * 32 + cc];
        }
        __syncthreads();
        const size_t row = rowBase + tid;
        const float dv = dec ? dec[row * SEG] : 0.f;

        for (int g32 = 0; g32 < 4; g32++) {
            if (pre) {
#pragma unroll 4
                for (int i = 0; i < 32; i++) {
                    int idx = i * 128 + tid, r = idx >> 5, cc = idx & 31;
                    spre[r * 33 + cc] = pre[(rowBase + r) * FOURH + nb * 128 + g32 * 32 + cc];
                }
            }
            __syncthreads();
            uint32_t dr[32];
            TCGEN05_LD_32X32B_X32(dr, tmem_base + g32 * 32);
            TCGEN05_WAIT_LD();
#pragma unroll
            for (int jj = 0; jj < 8; jj++) {
                int nl = g32 * 8 + jj;
                int hg = nb * 32 + nl;
                float zi = __uint_as_float(dr[jj * 4 + 0]) + bias[hg];
                float zf = __uint_as_float(dr[jj * 4 + 1]) + bias[512 + hg];
                float zg = __uint_as_float(dr[jj * 4 + 2]) + bias[1024 + hg];
                float zo = __uint_as_float(dr[jj * 4 + 3]) + bias[1536 + hg];
                if (pre) {
                    zi += spre[tid * 33 + jj * 4 + 0];
                    zf += spre[tid * 33 + jj * 4 + 1];
                    zg += spre[tid * 33 + jj * 4 + 2];
                    zo += spre[tid * 33 + jj * 4 + 3];
                }
                if (dec) {
                    zi += dv * dW0[hg];
                    zf += dv * dW0[512 + hg];
                    zg += dv * dW0[1024 + hg];
                    zo += dv * dW0[1536 + hg];
                }
                float cn, h;
                lstm_gates(zi, zf, zg, zo, scf[tid * 33 + nl], cn, h);
                scf[tid * 33 + nl] = cn;
                __nv_bfloat16 hh = __float2bfloat16(h);
                shi[tid * 34 + nl] = hh;
                slo[tid * 34 + nl] = __float2bfloat16(h - __bfloat162float(hh));
            }
            __syncthreads();
        }
#pragma unroll 4
        for (int i = 0; i < 32; i++) {
            int idx = i * 128 + tid, r = idx >> 5, cc = idx & 31;
            size_t o = (rowBase + r) * Hdim + nb * 32 + cc;
            c_state[o] = scf[r * 33 + cc];
            ohi[o] = shi[r * 34 + cc];
            olo[o] = slo[r * 34 + cc];
        }
    } else {
        for (int g32 = 0; g32 < 4; g32++) {
            uint32_t dr[32];
            TCGEN05_LD_32X32B_X32(dr, tmem_base + g32 * 32);
            TCGEN05_WAIT_LD();
#pragma unroll
            for (int j = 0; j < 32; j++) spre[tid * 33 + j] = __uint_as_float(dr[j]);
            __syncthreads();
#pragma unroll 4
            for (int i = 0; i < 32; i++) {
                int idx = i * 128 + tid, r = idx >> 5, cc = idx & 31;
                outC[(rowBase + r) * FOURH + nb * 128 + g32 * 32 + cc] = spre[r * 33 + cc];
            }
            __syncthreads();
        }
    }

    __syncthreads();
    if (tid < 32) TCGEN05_DEALLOC(tmem_base, 128);

#else
    // =================== FFMA fallback (non-'a' pass) ===================
    float* sA = (float*)(smemc + 1024);           // [32][132]
    float* sB = (float*)(smemc + 1024 + 16896);   // [32][132]
    const int tr  = tid >> 3;    // 0..15 -> rows tr*8..tr*8+7
    const int tc8 = tid & 7;     // 0..7  -> 8 cols per pass

    const float dv = (mode == 1 && dec) ? dec[0] : 0.f;  // placeholder, real below

    for (int pass = 0; pass < 2; pass++) {
        float acc[8][8];
#pragma unroll
        for (int r = 0; r < 8; r++)
#pragma unroll
            for (int j = 0; j < 8; j++) acc[r][j] = 0.f;

        for (int k0 = 0; k0 < kA; k0 += 32) {
            __syncthreads();
#pragma unroll 4
            for (int i = 0; i < 32; i++) {
                int idx = i * 128 + tid;
                int r = idx >> 5, kk = idx & 31;
                size_t ao = (rowBase + r) * (size_t)kA + k0 + kk;
                size_t bo = ((size_t)nb * 128 + r) * (size_t)kA + k0 + kk;
                sA[kk * 132 + r] = __bfloat162float(Ahi[ao]) + __bfloat162float(Alo[ao]);
                sB[kk * 132 + r] = __bfloat162float(Bhi[bo]) + __bfloat162float(Blo[bo]);
            }
            __syncthreads();
#pragma unroll
            for (int k = 0; k < 32; k++) {
                float a[8], b[8];
#pragma unroll
                for (int r = 0; r < 8; r++) a[r] = sA[k * 132 + tr * 8 + r];
#pragma unroll
                for (int j = 0; j < 8; j++) b[j] = sB[k * 132 + pass * 64 + tc8 * 8 + j];
#pragma unroll
                for (int r = 0; r < 8; r++)
#pragma unroll
                    for (int j = 0; j < 8; j++) acc[r][j] += a[r] * b[j];
            }
        }
        __syncthreads();

        if (mode == 0) {
#pragma unroll
            for (int r = 0; r < 8; r++)
#pragma unroll
                for (int j = 0; j < 8; j++)
                    outC[(rowBase + tr * 8 + r) * FOURH + nb * 128 + pass * 64 + tc8 * 8 + j]
                        = acc[r][j];
        } else {
            // each thread holds complete gate quads for 2 hcols x 8 rows
#pragma unroll
            for (int r = 0; r < 8; r++) {
                size_t row = rowBase + tr * 8 + r;
                float dvr = dec ? dec[row * SEG] : 0.f;
#pragma unroll
                for (int q = 0; q < 2; q++) {
                    int nl = pass * 16 + tc8 * 2 + q;
                    int hg = nb * 32 + nl;
                    float zi = acc[r][q * 4 + 0] + bias[hg];
                    float zf = acc[r][q * 4 + 1] + bias[512 + hg];
                    float zg = acc[r][q * 4 + 2] + bias[1024 + hg];
                    float zo = acc[r][q * 4 + 3] + bias[1536 + hg];
                    if (pre) {
                        const float* p = pre + row * FOURH + nb * 128 + pass * 64 + tc8 * 8;
                        zi += p[q * 4 + 0];
                        zf += p[q * 4 + 1];
                        zg += p[q * 4 + 2];
                        zo += p[q * 4 + 3];
                    }
                    if (dec) {
                        zi += dvr * dW0[hg];
                        zf += dvr * dW0[512 + hg];
                        zg += dvr * dW0[1024 + hg];
                        zo += dvr * dW0[1536 + hg];
                    }
                    size_t o = row * Hdim + hg;
                    float cn, h;
                    lstm_gates(zi, zf, zg, zo, c_state[o], cn, h);
                    c_state[o] = cn;
                    __nv_bfloat16 hh = __float2bfloat16(h);
                    ohi[o] = hh;
                    olo[o] = __float2bfloat16(h - __bfloat162float(hh));
                }
            }
        }
    }
    (void)dv;
#endif
}

// ---------------------------------------------------------------------------
// Final Dense(1): reads h = hi + lo from decoder L1 chain
// ---------------------------------------------------------------------------
__global__ void __launch_bounds__(256) dense_kernel(
    const __nv_bfloat16* __restrict__ hi, const __nv_bfloat16* __restrict__ lo,
    const float* __restrict__ W, const float* __restrict__ bb, float* __restrict__ out)
{
    int wid = (blockIdx.x * blockDim.x + threadIdx.x) >> 5;
    int lane = threadIdx.x & 31;
    if (wid >= Bsz * SEG) return;
    int b = wid / SEG, s = wid % SEG;
    size_t base = (size_t)(TENC + 1 + s) * BH + (size_t)b * Hdim;
    float sum = 0.f;
#pragma unroll 4
    for (int k = lane; k < Hdim; k += 32)
        sum += (__bfloat162float(hi[base + k]) + __bfloat162float(lo[base + k])) * W[k];
#pragma unroll
    for (int o = 16; o > 0; o >>= 1) sum += __shfl_down_sync(0xffffffffu, sum, o);
    if (lane == 0) out[(size_t)b * SEG + s] = sum + bb[0];
}

// ---------------------------------------------------------------------------
// Host launch
// ---------------------------------------------------------------------------
#define SMEM_BYTES 67584

extern "C" void kernel_launch(void* const* d_in, const int* in_sizes, int n_in,
                              void* d_out, int out_size)
{
    const float* x      = (const float*)d_in[0];
    const float* decin  = (const float*)d_in[1];
    const float* eW0    = (const float*)d_in[2];
    const float* eU0    = (const float*)d_in[3];
    const float* eb0    = (const float*)d_in[4];
    const float* eW1    = (const float*)d_in[5];
    const float* eU1    = (const float*)d_in[6];
    const float* eb1    = (const float*)d_in[7];
    const float* dW0    = (const float*)d_in[8];
    const float* dU0    = (const float*)d_in[9];
    const float* db0    = (const float*)d_in[10];
    const float* dW1    = (const float*)d_in[11];
    const float* dU1    = (const float*)d_in[12];
    const float* db1    = (const float*)d_in[13];
    const float* denseW = (const float*)d_in[14];
    const float* denseb = (const float*)d_in[15];
    float* out = (float*)d_out;

    cudaFuncSetAttribute(tc_gemm, cudaFuncAttributeMaxDynamicSharedMemorySize, SMEM_BYTES);

    float *pre, *c0, *c1;
    __nv_bfloat16 *h0h, *h0l, *h1h, *h1l, *xh, *xl;
    __nv_bfloat16 *eU0h, *eU0l, *eU1h, *eU1l, *dU0h, *dU0l, *dU1h, *dU1l;
    __nv_bfloat16 *eW1h, *eW1l, *dW1h, *dW1l, *eW0h, *eW0l;
    cudaGetSymbolAddress((void**)&pre, g_pre);
    cudaGetSymbolAddress((void**)&c0, g_c0);
    cudaGetSymbolAddress((void**)&c1, g_c1);
    cudaGetSymbolAddress((void**)&h0h, g_h0hi);
    cudaGetSymbolAddress((void**)&h0l, g_h0lo);
    cudaGetSymbolAddress((void**)&h1h, g_h1hi);
    cudaGetSymbolAddress((void**)&h1l, g_h1lo);
    cudaGetSymbolAddress((void**)&xh, g_xhi);
    cudaGetSymbolAddress((void**)&xl, g_xlo);
    cudaGetSymbolAddress((void**)&eU0h, g_eU0h); cudaGetSymbolAddress((void**)&eU0l, g_eU0l);
    cudaGetSymbolAddress((void**)&eU1h, g_eU1h); cudaGetSymbolAddress((void**)&eU1l, g_eU1l);
    cudaGetSymbolAddress((void**)&dU0h, g_dU0h); cudaGetSymbolAddress((void**)&dU0l, g_dU0l);
    cudaGetSymbolAddress((void**)&dU1h, g_dU1h); cudaGetSymbolAddress((void**)&dU1l, g_dU1l);
    cudaGetSymbolAddress((void**)&eW1h, g_eW1h); cudaGetSymbolAddress((void**)&eW1l, g_eW1l);
    cudaGetSymbolAddress((void**)&dW1h, g_dW1h); cudaGetSymbolAddress((void**)&dW1l, g_dW1l);
    cudaGetSymbolAddress((void**)&eW0h, g_eW0h); cudaGetSymbolAddress((void**)&eW0l, g_eW0l);

    // --- conversions ---
    int wblk = (2048 * 512 + 255) / 256;
    conv_weight<<<wblk, 256>>>(eU0, eU0h, eU0l, 512, 512);
    conv_weight<<<wblk, 256>>>(eU1, eU1h, eU1l, 512, 512);
    conv_weight<<<wblk, 256>>>(dU0, dU0h, dU0l, 512, 512);
    conv_weight<<<wblk, 256>>>(dU1, dU1h, dU1l, 512, 512);
    conv_weight<<<wblk, 256>>>(eW1, eW1h, eW1l, 512, 512);
    conv_weight<<<wblk, 256>>>(dW1, dW1h, dW1l, 512, 512);
    conv_weight<<<(2048 * 128 + 255) / 256, 256>>>(eW0, eW0h, eW0l, 121, 128);
    conv_x<<<(int)(((size_t)65536 * 128 + 255) / 256), 256>>>(x, xh, xl);

    // --- zero initial states ---
    cudaMemsetAsync(h0h, 0, (size_t)BH * sizeof(__nv_bfloat16));
    cudaMemsetAsync(h0l, 0, (size_t)BH * sizeof(__nv_bfloat16));
    cudaMemsetAsync(h1h, 0, (size_t)BH * sizeof(__nv_bfloat16));
    cudaMemsetAsync(h1l, 0, (size_t)BH * sizeof(__nv_bfloat16));
    cudaMemsetAsync(c0, 0, (size_t)BH * sizeof(float));
    cudaMemsetAsync(c1, 0, (size_t)BH * sizeof(float));

    dim3 gStep(16, 8);

    // --- pre0 = X @ eW0 ---
    tc_gemm<<<dim3(16, 512), 128, SMEM_BYTES>>>(
        xh, xl, eW0h, eW0l, nullptr, nullptr, nullptr, nullptr,
        nullptr, nullptr, nullptr, pre, 128, 0);

    // --- encoder layer 0 ---
    for (int t = 0; t < TENC; t++)
        tc_gemm<<<gStep, 128, SMEM_BYTES>>>(
            h0h + (size_t)t * BH, h0l + (size_t)t * BH, eU0h, eU0l,
            pre + (size_t)t * Bsz * FOURH, eb0, nullptr, nullptr,
            c0, h0h + (size_t)(t + 1) * BH, h0l + (size_t)(t + 1) * BH,
            nullptr, 512, 1);

    // --- pre1 = y0 @ eW1 ---
    tc_gemm<<<dim3(16, 512), 128, SMEM_BYTES>>>(
        h0h + (size_t)BH, h0l + (size_t)BH, eW1h, eW1l, nullptr, nullptr, nullptr, nullptr,
        nullptr, nullptr, nullptr, pre, 512, 0);

    // --- encoder layer 1 ---
    for (int t = 0; t < TENC; t++)
        tc_gemm<<<gStep, 128, SMEM_BYTES>>>(
            h1h + (size_t)t * BH, h1l + (size_t)t * BH, eU1h, eU1l,
            pre + (size_t)t * Bsz * FOURH, eb1, nullptr, nullptr,
            c1, h1h + (size_t)(t + 1) * BH, h1l + (size_t)(t + 1) * BH,
            nullptr, 512, 1);

    // --- decoder layer 0 (dec_in scalar as rank-1 add in epilogue) ---
    for (int t = 0; t < SEG; t++)
        tc_gemm<<<gStep, 128, SMEM_BYTES>>>(
            h0h + (size_t)(TENC + t) * BH, h0l + (size_t)(TENC + t) * BH, dU0h, dU0l,
            nullptr, db0, decin + t, dW0,
            c0, h0h + (size_t)(TENC + 1 + t) * BH, h0l + (size_t)(TENC + 1 + t) * BH,
            nullptr, 512, 1);

    // --- pre_d1 = d0 @ dW1 ---
    tc_gemm<<<dim3(16, 256), 128, SMEM_BYTES>>>(
        h0h + (size_t)(TENC + 1) * BH, h0l + (size_t)(TENC + 1) * BH, dW1h, dW1l,
        nullptr, nullptr, nullptr, nullptr,
        nullptr, nullptr, nullptr, pre, 512, 0);

    // --- decoder layer 1 ---
    for (int t = 0; t < SEG; t++)
        tc_gemm<<<gStep, 128, SMEM_BYTES>>>(
            h1h + (size_t)(TENC + t) * BH, h1l + (size_t)(TENC + t) * BH, dU1h, dU1l,
            pre + (size_t)t * Bsz * FOURH, db1, nullptr, nullptr,
            c1, h1h + (size_t)(TENC + 1 + t) * BH, h1l + (size_t)(TENC + 1 + t) * BH,
            nullptr, 512, 1);

    // --- final dense ---
    dense_kernel<<<(Bsz * SEG * 32) / 256, 256>>>(h1h, h1l, denseW, denseb, out);
}

// round 6
// speedup vs baseline: 2.3872x; 1.5001x over previous
#include <cuda_runtime.h>
#include <cuda_bf16.h>
#include <math.h>
#include <stdint.h>

#define Bsz   1024
#define TENC  64
#define SEG   32
#define Hdim  512
#define FOURH 2048
#define BH    (Bsz * Hdim)

// Does this device pass have tcgen05 (arch-specific 'a' / family 'f')?
#if defined(__CUDA_ARCH__) && (defined(__CUDA_ARCH_FEAT_SM103_ALL) || \
    defined(__CUDA_ARCH_FEAT_SM100_ALL) || defined(__CUDA_ARCH_SPECIFIC__) || \
    defined(__CUDA_ARCH_FAMILY_SPECIFIC__))
#define TC_OK 1
#else
#define TC_OK 0
#endif

// ---------------------------------------------------------------------------
// Static device scratch
// ---------------------------------------------------------------------------
__device__ float g_pre[(size_t)TENC * Bsz * FOURH];              // permuted cols
__device__ __nv_bfloat16 g_h0hi[(size_t)97 * BH];
__device__ __nv_bfloat16 g_h0lo[(size_t)97 * BH];
__device__ __nv_bfloat16 g_h1hi[(size_t)97 * BH];
__device__ __nv_bfloat16 g_h1lo[(size_t)97 * BH];
__device__ float g_c0[BH];
__device__ float g_c1[BH];
__device__ __nv_bfloat16 g_xhi[(size_t)65536 * 128];
__device__ __nv_bfloat16 g_xlo[(size_t)65536 * 128];
__device__ __nv_bfloat16 g_eU0h[(size_t)2048 * 512], g_eU0l[(size_t)2048 * 512];
__device__ __nv_bfloat16 g_eU1h[(size_t)2048 * 512], g_eU1l[(size_t)2048 * 512];
__device__ __nv_bfloat16 g_dU0h[(size_t)2048 * 512], g_dU0l[(size_t)2048 * 512];
__device__ __nv_bfloat16 g_dU1h[(size_t)2048 * 512], g_dU1l[(size_t)2048 * 512];
__device__ __nv_bfloat16 g_eW1h[(size_t)2048 * 512], g_eW1l[(size_t)2048 * 512];
__device__ __nv_bfloat16 g_dW1h[(size_t)2048 * 512], g_dW1l[(size_t)2048 * 512];
__device__ __nv_bfloat16 g_eW0h[(size_t)2048 * 128], g_eW0l[(size_t)2048 * 128];

// ---------------------------------------------------------------------------
// Helpers
// ---------------------------------------------------------------------------
__device__ __forceinline__ uint32_t smem_to_u32(const void* p) {
    uint32_t a;
    asm("{ .reg .u64 t; cvta.to.shared.u64 t, %1; cvt.u32.u64 %0, t; }" : "=r"(a) : "l"(p));
    return a;
}

__device__ __forceinline__ void lstm_gates(float zi, float zf, float zg, float zo,
                                           float cold, float& cn, float& h) {
    float ig = 1.f / (1.f + expf(-zi));
    float fg = 1.f / (1.f + expf(-zf));
    float gg = tanhf(zg);
    float og = 1.f / (1.f + expf(-zo));
    cn = fg * cold + ig * gg;
    h  = og * tanhf(cn);
}

#if TC_OK
__device__ __forceinline__ uint32_t elect_one_pred() {
    uint32_t pred;
    asm volatile(
        "{\n\t.reg .pred p;\n\t"
        "elect.sync _|p, 0xFFFFFFFF;\n\t"
        "selp.b32 %0, 1, 0, p;\n\t}"
        : "=r"(pred));
    return pred;
}

#define TCGEN05_ALLOC(addr, n) \
    asm volatile("tcgen05.alloc.cta_group::1.sync.aligned.shared::cta.b32 [%0], %1;" \
                 :: "r"((uint32_t)(addr)), "r"((uint32_t)(n)) : "memory")
#define TCGEN05_DEALLOC(tm, n) \
    asm volatile("tcgen05.dealloc.cta_group::1.sync.aligned.b32 %0, %1;" :: "r"(tm), "r"((uint32_t)(n)))
#define TCGEN05_RELINQ() \
    asm volatile("tcgen05.relinquish_alloc_permit.cta_group::1.sync.aligned;")
#define TCGEN05_COMMIT(mb) \
    asm volatile("tcgen05.commit.cta_group::1.mbarrier::arrive::one.shared::cluster.b64 [%0];" \
                 :: "r"((uint32_t)(mb)) : "memory")
#define TCGEN05_WAIT_LD() asm volatile("tcgen05.wait::ld.sync.aligned;" ::: "memory")
#define TCGEN05_FENCE_AFTER() asm volatile("tcgen05.fence::after_thread_sync;" ::: "memory")
#define MBARRIER_INIT(mb, cnt) \
    asm volatile("mbarrier.init.shared.b64 [%0], %1;" :: "r"((uint32_t)(mb)), "r"((uint32_t)(cnt)) : "memory")
#define FENCE_PROXY_ASYNC() asm volatile("fence.proxy.async.shared::cta;" ::: "memory")

#define CP_ASYNC16(dst, src) \
    asm volatile("cp.async.cg.shared.global [%0], [%1], 16;" :: "r"((uint32_t)(dst)), "l"(src) : "memory")
#define CP_COMMIT() asm volatile("cp.async.commit_group;" ::: "memory")
#define CP_WAIT(n)  asm volatile("cp.async.wait_group %0;" :: "n"(n) : "memory")

#define MBARRIER_WAIT_PARITY(mbar_smem_addr, phase_parity) do { \
    uint32_t _mbar = (uint32_t)(mbar_smem_addr); \
    uint32_t _parity = (uint32_t)(phase_parity); \
    uint32_t _done; \
    asm volatile( \
        "{\n\t.reg .pred p;\n\t" \
        "mbarrier.try_wait.parity.acquire.cta.shared::cta.b64 p, [%1], %2;\n\t" \
        "selp.b32 %0, 1, 0, p;\n\t}" \
        : "=r"(_done) : "r"(_mbar), "r"(_parity) : "memory"); \
    if (!_done) { \
        asm volatile( \
            "{\n\t.reg .pred P1;\n\t" \
            "WAIT_LOOP_%=:\n\t" \
            "mbarrier.try_wait.parity.acquire.cta.shared::cta.b64 P1, [%0], %1, 0x989680;\n\t" \
            "@P1 bra.uni WAIT_DONE_%=;\n\t" \
            "bra.uni WAIT_LOOP_%=;\n\t" \
            "WAIT_DONE_%=:\n\t}" \
            :: "r"(_mbar), "r"(_parity) : "memory"); \
    } \
} while (0)

#define TCGEN05_LD_32X32B_X32(r, tmem_addr) \
    asm volatile( \
        "tcgen05.ld.sync.aligned.32x32b.x32.b32 " \
        "{%0, %1, %2, %3, %4, %5, %6, %7, " \
        " %8, %9, %10, %11, %12, %13, %14, %15, " \
        " %16, %17, %18, %19, %20, %21, %22, %23, " \
        " %24, %25, %26, %27, %28, %29, %30, %31}, [%32];" \
        : "=r"((r)[0]),  "=r"((r)[1]),  "=r"((r)[2]),  "=r"((r)[3]), \
          "=r"((r)[4]),  "=r"((r)[5]),  "=r"((r)[6]),  "=r"((r)[7]), \
          "=r"((r)[8]),  "=r"((r)[9]),  "=r"((r)[10]), "=r"((r)[11]), \
          "=r"((r)[12]), "=r"((r)[13]), "=r"((r)[14]), "=r"((r)[15]), \
          "=r"((r)[16]), "=r"((r)[17]), "=r"((r)[18]), "=r"((r)[19]), \
          "=r"((r)[20]), "=r"((r)[21]), "=r"((r)[22]), "=r"((r)[23]), \
          "=r"((r)[24]), "=r"((r)[25]), "=r"((r)[26]), "=r"((r)[27]), \
          "=r"((r)[28]), "=r"((r)[29]), "=r"((r)[30]), "=r"((r)[31]) \
        : "r"(tmem_addr))

static constexpr uint64_t SMEM_DESC_BASE_SW128 =
    (uint64_t(2)  << 61) | (uint64_t(1) << 46) | (uint64_t(64) << 32) | (uint64_t(1) << 16);
#define MAKE_SMEM_DESC(a) (SMEM_DESC_BASE_SW128 | ((uint64_t)((a) >> 4) & 0x3FFF))

// idesc kind::f16: dtype F32, atype/btype BF16, N=128, M=128
#define MMA_IDESC 0x8200490u

__device__ __forceinline__ void mma_f16_ss(uint32_t d, uint64_t a, uint64_t b,
                                           uint32_t idesc, bool acc) {
    uint32_t en = acc ? 1u : 0u;
    asm volatile(
        "{\n\t.reg .pred p;\n\t"
        "setp.ne.u32 p, %5, 0;\n\t"
        "tcgen05.mma.cta_group::1.kind::f16 [%0], %1, %2, %3, {%4, %4, %4, %4}, p;\n\t}"
        :: "r"(d), "l"(a), "l"(b), "r"(idesc), "r"(0u), "r"(en) : "memory");
}
#endif // TC_OK

// ---------------------------------------------------------------------------
// Weight conversion: U[K][2048] fp32 -> B-format [2048 permuted N][Kpad] bf16 hi/lo
// permuted n: hT=n>>7, r=n&127, g=r&3, nl=r>>2, orig = g*512 + hT*32 + nl
// ---------------------------------------------------------------------------
__global__ void __launch_bounds__(256) conv_weight(
    const float* __restrict__ U, __nv_bfloat16* __restrict__ bh,
    __nv_bfloat16* __restrict__ bl, int K, int Kpad)
{
    int idx = blockIdx.x * 256 + threadIdx.x;
    if (idx >= 2048 * Kpad) return;
    int n = idx / Kpad, k = idx % Kpad;
    int r = n & 127, hT = n >> 7;
    int g = r & 3, nl = r >> 2;
    int orig = g * 512 + hT * 32 + nl;
    float v = (k < K) ? U[(size_t)k * FOURH + orig] : 0.f;
    __nv_bfloat16 h = __float2bfloat16(v);
    bh[idx] = h;
    bl[idx] = __float2bfloat16(v - __bfloat162float(h));
}

// x[b][t][121] -> rows m=t*1024+b, [m][128] bf16 hi/lo (zero-padded K)
__global__ void __launch_bounds__(256) conv_x(
    const float* __restrict__ x, __nv_bfloat16* __restrict__ xh, __nv_bfloat16* __restrict__ xl)
{
    size_t idx = (size_t)blockIdx.x * 256 + threadIdx.x;
    if (idx >= (size_t)65536 * 128) return;
    int m = (int)(idx >> 7), k = (int)(idx & 127);
    int t = m >> 10, b = m & 1023;
    float v = (k < 121) ? x[(size_t)b * (TENC * 121) + t * 121 + k] : 0.f;
    __nv_bfloat16 h = __float2bfloat16(v);
    xh[idx] = h;
    xl[idx] = __float2bfloat16(v - __bfloat162float(h));
}

// ---------------------------------------------------------------------------
// GEMM (split-bf16): D = Ahi@Bhi^T + Alo@Bhi^T + Ahi@Blo^T
// TC path: per 64-K chunk load {Ahi,Alo,Bhi,Blo} ONCE via cp.async (3-stage
// pipeline), issue 12 MMAs. mode 0: D -> outC. mode 1: LSTM epilogue.
// ---------------------------------------------------------------------------
__global__ void __launch_bounds__(128) tc_gemm(
    const __nv_bfloat16* __restrict__ Ahi, const __nv_bfloat16* __restrict__ Alo,
    const __nv_bfloat16* __restrict__ Bhi, const __nv_bfloat16* __restrict__ Blo,
    const float* __restrict__ pre,
    const float* __restrict__ bias,
    const float* __restrict__ dec, const float* __restrict__ dW0,
    float* __restrict__ c_state,
    __nv_bfloat16* __restrict__ ohi, __nv_bfloat16* __restrict__ olo,
    float* __restrict__ outC,
    int kA, int mode)
{
    extern __shared__ char smem[];
    const uint32_t sb = smem_to_u32(smem);
    const uint32_t tb = (sb + 1023u) & ~1023u;
    char* smemc = smem + (tb - sb);

    const int tid = threadIdx.x;
    const int nb = blockIdx.x;
    const size_t rowBase = (size_t)blockIdx.y * 128;

#if TC_OK
    // =================== tcgen05 path ===================
    const uint32_t MBF = tb + 8;
    // per-stage mma-done barriers at tb+16, tb+24, tb+32

    if (tid < 32) {
        TCGEN05_ALLOC(tb, 128);
        TCGEN05_RELINQ();
    }
    if (tid == 0) {
        MBARRIER_INIT(MBF, 1);
        MBARRIER_INIT(tb + 16, 1);
        MBARRIER_INIT(tb + 24, 1);
        MBARRIER_INIT(tb + 32, 1);
    }
    __syncthreads();
    uint32_t tmem_base;
    asm volatile("ld.shared.b32 %0, [%1];" : "=r"(tmem_base) : "r"(tb));

    const int nch = kA >> 6;       // 8 (K=512) or 2 (K=128)
    int wph0 = 0, wph1 = 0, wph2 = 0;

    // chunk loader: stage buf = cc%3 at tb+1024+buf*65536 {Ahi,Alo,Bhi,Blo}
#define LOAD_CHUNK(cc) do { \
        const int _buf = (cc) % 3; \
        const uint32_t _st = tb + 1024 + _buf * 65536; \
        const int _ko = (cc) * 64; \
        _Pragma("unroll") \
        for (int _i = 0; _i < 8; _i++) { \
            int _idx = _i * 128 + tid; \
            int _r = _idx >> 3, _s = _idx & 7; \
            uint32_t _off = (uint32_t)(_r * 128 + _s * 16); \
            uint32_t _sw = _off ^ ((_off >> 3) & 0x70); \
            size_t _ga = (rowBase + _r) * (size_t)kA + _ko + _s * 8; \
            size_t _gb = ((size_t)nb * 128 + _r) * (size_t)kA + _ko + _s * 8; \
            CP_ASYNC16(_st + _sw,         Ahi + _ga); \
            CP_ASYNC16(_st + 16384 + _sw, Alo + _ga); \
            CP_ASYNC16(_st + 32768 + _sw, Bhi + _gb); \
            CP_ASYNC16(_st + 49152 + _sw, Blo + _gb); \
        } \
        CP_COMMIT(); \
    } while (0)

    LOAD_CHUNK(0);
    if (nch > 1) LOAD_CHUNK(1);

    for (int c = 0; c < nch; c++) {
        const int nl = c + 2;
        if (nl < nch) {
            const int b = nl % 3;
            if (c >= 1) {
                // buffer b was used by chunk c-1; wait its MMA completion
                if (b == 0)      { MBARRIER_WAIT_PARITY(tb + 16, wph0 & 1); wph0++; }
                else if (b == 1) { MBARRIER_WAIT_PARITY(tb + 24, wph1 & 1); wph1++; }
                else             { MBARRIER_WAIT_PARITY(tb + 32, wph2 & 1); wph2++; }
            }
            LOAD_CHUNK(nl);
        }
        // ensure chunk c's cp.async group has landed
        int issued = (c + 3 < nch) ? (c + 3) : nch;
        int pend = issued - (c + 1);
        if (pend <= 0)      CP_WAIT(0);
        else if (pend == 1) CP_WAIT(1);
        else                CP_WAIT(2);
        FENCE_PROXY_ASYNC();
        __syncthreads();
        if (tid < 32) {
            if (elect_one_pred()) {
                const uint32_t st = tb + 1024 + (c % 3) * 65536;
                uint64_t adh = MAKE_SMEM_DESC(st);
                uint64_t adl = MAKE_SMEM_DESC(st + 16384);
                uint64_t bdh = MAKE_SMEM_DESC(st + 32768);
                uint64_t bdl = MAKE_SMEM_DESC(st + 49152);
#pragma unroll
                for (int j = 0; j < 4; j++)
                    mma_f16_ss(tmem_base, adh + j * 2, bdh + j * 2, MMA_IDESC, !(c == 0 && j == 0));
#pragma unroll
                for (int j = 0; j < 4; j++)
                    mma_f16_ss(tmem_base, adl + j * 2, bdh + j * 2, MMA_IDESC, true);
#pragma unroll
                for (int j = 0; j < 4; j++)
                    mma_f16_ss(tmem_base, adh + j * 2, bdl + j * 2, MMA_IDESC, true);
                TCGEN05_COMMIT(tb + 16 + (c % 3) * 8);
            }
        }
    }
#undef LOAD_CHUNK

    if (tid < 32) {
        if (elect_one_pred()) TCGEN05_COMMIT(MBF);
    }
    __syncthreads();
    MBARRIER_WAIT_PARITY(MBF, 0);
    TCGEN05_FENCE_AFTER();

    // ---- epilogue (GEMM smem now free) ----
    float* spre = (float*)(smemc + 1024);                  // 128 x 33 fp32
    float* scf  = (float*)(smemc + 17920);                 // 128 x 33 fp32
    __nv_bfloat16* shi = (__nv_bfloat16*)(smemc + 34816);  // 128 x 34 bf16
    __nv_bfloat16* slo = (__nv_bfloat16*)(smemc + 43520);  // 128 x 34 bf16

    if (mode == 1) {
#pragma unroll 4
        for (int i = 0; i < 32; i++) {
            int idx = i * 128 + tid, r = idx >> 5, cc = idx & 31;
            scf[r * 33 + cc] = c_state[(rowBase + r) * Hdim + nb * 32 + cc];
        }
        __syncthreads();
        const size_t row = rowBase + tid;
        const float dv = dec ? dec[row * SEG] : 0.f;

        for (int g32 = 0; g32 < 4; g32++) {
            if (pre) {
#pragma unroll 4
                for (int i = 0; i < 32; i++) {
                    int idx = i * 128 + tid, r = idx >> 5, cc = idx & 31;
                    spre[r * 33 + cc] = pre[(rowBase + r) * FOURH + nb * 128 + g32 * 32 + cc];
                }
            }
            __syncthreads();
            uint32_t dr[32];
            TCGEN05_LD_32X32B_X32(dr, tmem_base + g32 * 32);
            TCGEN05_WAIT_LD();
#pragma unroll
            for (int jj = 0; jj < 8; jj++) {
                int nl = g32 * 8 + jj;
                int hg = nb * 32 + nl;
                float zi = __uint_as_float(dr[jj * 4 + 0]) + bias[hg];
                float zf = __uint_as_float(dr[jj * 4 + 1]) + bias[512 + hg];
                float zg = __uint_as_float(dr[jj * 4 + 2]) + bias[1024 + hg];
                float zo = __uint_as_float(dr[jj * 4 + 3]) + bias[1536 + hg];
                if (pre) {
                    zi += spre[tid * 33 + jj * 4 + 0];
                    zf += spre[tid * 33 + jj * 4 + 1];
                    zg += spre[tid * 33 + jj * 4 + 2];
                    zo += spre[tid * 33 + jj * 4 + 3];
                }
                if (dec) {
                    zi += dv * dW0[hg];
                    zf += dv * dW0[512 + hg];
                    zg += dv * dW0[1024 + hg];
                    zo += dv * dW0[1536 + hg];
                }
                float cn, h;
                lstm_gates(zi, zf, zg, zo, scf[tid * 33 + nl], cn, h);
                scf[tid * 33 + nl] = cn;
                __nv_bfloat16 hh = __float2bfloat16(h);
                shi[tid * 34 + nl] = hh;
                slo[tid * 34 + nl] = __float2bfloat16(h - __bfloat162float(hh));
            }
            __syncthreads();
        }
#pragma unroll 4
        for (int i = 0; i < 32; i++) {
            int idx = i * 128 + tid, r = idx >> 5, cc = idx & 31;
            size_t o = (rowBase + r) * Hdim + nb * 32 + cc;
            c_state[o] = scf[r * 33 + cc];
            ohi[o] = shi[r * 34 + cc];
            olo[o] = slo[r * 34 + cc];
        }
    } else {
        for (int g32 = 0; g32 < 4; g32++) {
            uint32_t dr[32];
            TCGEN05_LD_32X32B_X32(dr, tmem_base + g32 * 32);
            TCGEN05_WAIT_LD();
#pragma unroll
            for (int j = 0; j < 32; j++) spre[tid * 33 + j] = __uint_as_float(dr[j]);
            __syncthreads();
#pragma unroll 4
            for (int i = 0; i < 32; i++) {
                int idx = i * 128 + tid, r = idx >> 5, cc = idx & 31;
                outC[(rowBase + r) * FOURH + nb * 128 + g32 * 32 + cc] = spre[r * 33 + cc];
            }
            __syncthreads();
        }
    }

    __syncthreads();
    if (tid < 32) TCGEN05_DEALLOC(tmem_base, 128);

#else
    // =================== FFMA fallback (non-'a' pass) ===================
    float* sA = (float*)(smemc + 1024);           // [32][132]
    float* sB = (float*)(smemc + 1024 + 16896);   // [32][132]
    const int tr  = tid >> 3;
    const int tc8 = tid & 7;

    for (int pass = 0; pass < 2; pass++) {
        float acc[8][8];
#pragma unroll
        for (int r = 0; r < 8; r++)
#pragma unroll
            for (int j = 0; j < 8; j++) acc[r][j] = 0.f;

        for (int k0 = 0; k0 < kA; k0 += 32) {
            __syncthreads();
#pragma unroll 4
            for (int i = 0; i < 32; i++) {
                int idx = i * 128 + tid;
                int r = idx >> 5, kk = idx & 31;
                size_t ao = (rowBase + r) * (size_t)kA + k0 + kk;
                size_t bo = ((size_t)nb * 128 + r) * (size_t)kA + k0 + kk;
                sA[kk * 132 + r] = __bfloat162float(Ahi[ao]) + __bfloat162float(Alo[ao]);
                sB[kk * 132 + r] = __bfloat162float(Bhi[bo]) + __bfloat162float(Blo[bo]);
            }
            __syncthreads();
#pragma unroll
            for (int k = 0; k < 32; k++) {
                float a[8], b[8];
#pragma unroll
                for (int r = 0; r < 8; r++) a[r] = sA[k * 132 + tr * 8 + r];
#pragma unroll
                for (int j = 0; j < 8; j++) b[j] = sB[k * 132 + pass * 64 + tc8 * 8 + j];
#pragma unroll
                for (int r = 0; r < 8; r++)
#pragma unroll
                    for (int j = 0; j < 8; j++) acc[r][j] += a[r] * b[j];
            }
        }
        __syncthreads();

        if (mode == 0) {
#pragma unroll
            for (int r = 0; r < 8; r++)
#pragma unroll
                for (int j = 0; j < 8; j++)
                    outC[(rowBase + tr * 8 + r) * FOURH + nb * 128 + pass * 64 + tc8 * 8 + j]
                        = acc[r][j];
        } else {
#pragma unroll
            for (int r = 0; r < 8; r++) {
                size_t row = rowBase + tr * 8 + r;
                float dvr = dec ? dec[row * SEG] : 0.f;
#pragma unroll
                for (int q = 0; q < 2; q++) {
                    int nl = pass * 16 + tc8 * 2 + q;
                    int hg = nb * 32 + nl;
                    float zi = acc[r][q * 4 + 0] + bias[hg];
                    float zf = acc[r][q * 4 + 1] + bias[512 + hg];
                    float zg = acc[r][q * 4 + 2] + bias[1024 + hg];
                    float zo = acc[r][q * 4 + 3] + bias[1536 + hg];
                    if (pre) {
                        const float* p = pre + row * FOURH + nb * 128 + pass * 64 + tc8 * 8;
                        zi += p[q * 4 + 0];
                        zf += p[q * 4 + 1];
                        zg += p[q * 4 + 2];
                        zo += p[q * 4 + 3];
                    }
                    if (dec) {
                        zi += dvr * dW0[hg];
                        zf += dvr * dW0[512 + hg];
                        zg += dvr * dW0[1024 + hg];
                        zo += dvr * dW0[1536 + hg];
                    }
                    size_t o = row * Hdim + hg;
                    float cn, h;
                    lstm_gates(zi, zf, zg, zo, c_state[o], cn, h);
                    c_state[o] = cn;
                    __nv_bfloat16 hh = __float2bfloat16(h);
                    ohi[o] = hh;
                    olo[o] = __float2bfloat16(h - __bfloat162float(hh));
                }
            }
        }
    }
#endif
}

// ---------------------------------------------------------------------------
// Final Dense(1): reads h = hi + lo from decoder L1 chain
// ---------------------------------------------------------------------------
__global__ void __launch_bounds__(256) dense_kernel(
    const __nv_bfloat16* __restrict__ hi, const __nv_bfloat16* __restrict__ lo,
    const float* __restrict__ W, const float* __restrict__ bb, float* __restrict__ out)
{
    int wid = (blockIdx.x * blockDim.x + threadIdx.x) >> 5;
    int lane = threadIdx.x & 31;
    if (wid >= Bsz * SEG) return;
    int b = wid / SEG, s = wid % SEG;
    size_t base = (size_t)(TENC + 1 + s) * BH + (size_t)b * Hdim;
    float sum = 0.f;
#pragma unroll 4
    for (int k = lane; k < Hdim; k += 32)
        sum += (__bfloat162float(hi[base + k]) + __bfloat162float(lo[base + k])) * W[k];
#pragma unroll
    for (int o = 16; o > 0; o >>= 1) sum += __shfl_down_sync(0xffffffffu, sum, o);
    if (lane == 0) out[(size_t)b * SEG + s] = sum + bb[0];
}

// ---------------------------------------------------------------------------
// Host launch
// ---------------------------------------------------------------------------
#define SMEM_BYTES (1024 + 3 * 65536)   // 197632

extern "C" void kernel_launch(void* const* d_in, const int* in_sizes, int n_in,
                              void* d_out, int out_size)
{
    const float* x      = (const float*)d_in[0];
    const float* decin  = (const float*)d_in[1];
    const float* eW0    = (const float*)d_in[2];
    const float* eU0    = (const float*)d_in[3];
    const float* eb0    = (const float*)d_in[4];
    const float* eW1    = (const float*)d_in[5];
    const float* eU1    = (const float*)d_in[6];
    const float* eb1    = (const float*)d_in[7];
    const float* dW0    = (const float*)d_in[8];
    const float* dU0    = (const float*)d_in[9];
    const float* db0    = (const float*)d_in[10];
    const float* dW1    = (const float*)d_in[11];
    const float* dU1    = (const float*)d_in[12];
    const float* db1    = (const float*)d_in[13];
    const float* denseW = (const float*)d_in[14];
    const float* denseb = (const float*)d_in[15];
    float* out = (float*)d_out;

    cudaFuncSetAttribute(tc_gemm, cudaFuncAttributeMaxDynamicSharedMemorySize, SMEM_BYTES);

    float *pre, *c0, *c1;
    __nv_bfloat16 *h0h, *h0l, *h1h, *h1l, *xh, *xl;
    __nv_bfloat16 *eU0h, *eU0l, *eU1h, *eU1l, *dU0h, *dU0l, *dU1h, *dU1l;
    __nv_bfloat16 *eW1h, *eW1l, *dW1h, *dW1l, *eW0h, *eW0l;
    cudaGetSymbolAddress((void**)&pre, g_pre);
    cudaGetSymbolAddress((void**)&c0, g_c0);
    cudaGetSymbolAddress((void**)&c1, g_c1);
    cudaGetSymbolAddress((void**)&h0h, g_h0hi);
    cudaGetSymbolAddress((void**)&h0l, g_h0lo);
    cudaGetSymbolAddress((void**)&h1h, g_h1hi);
    cudaGetSymbolAddress((void**)&h1l, g_h1lo);
    cudaGetSymbolAddress((void**)&xh, g_xhi);
    cudaGetSymbolAddress((void**)&xl, g_xlo);
    cudaGetSymbolAddress((void**)&eU0h, g_eU0h); cudaGetSymbolAddress((void**)&eU0l, g_eU0l);
    cudaGetSymbolAddress((void**)&eU1h, g_eU1h); cudaGetSymbolAddress((void**)&eU1l, g_eU1l);
    cudaGetSymbolAddress((void**)&dU0h, g_dU0h); cudaGetSymbolAddress((void**)&dU0l, g_dU0l);
    cudaGetSymbolAddress((void**)&dU1h, g_dU1h); cudaGetSymbolAddress((void**)&dU1l, g_dU1l);
    cudaGetSymbolAddress((void**)&eW1h, g_eW1h); cudaGetSymbolAddress((void**)&eW1l, g_eW1l);
    cudaGetSymbolAddress((void**)&dW1h, g_dW1h); cudaGetSymbolAddress((void**)&dW1l, g_dW1l);
    cudaGetSymbolAddress((void**)&eW0h, g_eW0h); cudaGetSymbolAddress((void**)&eW0l, g_eW0l);

    // --- conversions ---
    int wblk = (2048 * 512 + 255) / 256;
    conv_weight<<<wblk, 256>>>(eU0, eU0h, eU0l, 512, 512);
    conv_weight<<<wblk, 256>>>(eU1, eU1h, eU1l, 512, 512);
    conv_weight<<<wblk, 256>>>(dU0, dU0h, dU0l, 512, 512);
    conv_weight<<<wblk, 256>>>(dU1, dU1h, dU1l, 512, 512);
    conv_weight<<<wblk, 256>>>(eW1, eW1h, eW1l, 512, 512);
    conv_weight<<<wblk, 256>>>(dW1, dW1h, dW1l, 512, 512);
    conv_weight<<<(2048 * 128 + 255) / 256, 256>>>(eW0, eW0h, eW0l, 121, 128);
    conv_x<<<(int)(((size_t)65536 * 128 + 255) / 256), 256>>>(x, xh, xl);

    // --- zero initial states ---
    cudaMemsetAsync(h0h, 0, (size_t)BH * sizeof(__nv_bfloat16));
    cudaMemsetAsync(h0l, 0, (size_t)BH * sizeof(__nv_bfloat16));
    cudaMemsetAsync(h1h, 0, (size_t)BH * sizeof(__nv_bfloat16));
    cudaMemsetAsync(h1l, 0, (size_t)BH * sizeof(__nv_bfloat16));
    cudaMemsetAsync(c0, 0, (size_t)BH * sizeof(float));
    cudaMemsetAsync(c1, 0, (size_t)BH * sizeof(float));

    dim3 gStep(16, 8);

    // --- pre0 = X @ eW0 ---
    tc_gemm<<<dim3(16, 512), 128, SMEM_BYTES>>>(
        xh, xl, eW0h, eW0l, nullptr, nullptr, nullptr, nullptr,
        nullptr, nullptr, nullptr, pre, 128, 0);

    // --- encoder layer 0 ---
    for (int t = 0; t < TENC; t++)
        tc_gemm<<<gStep, 128, SMEM_BYTES>>>(
            h0h + (size_t)t * BH, h0l + (size_t)t * BH, eU0h, eU0l,
            pre + (size_t)t * Bsz * FOURH, eb0, nullptr, nullptr,
            c0, h0h + (size_t)(t + 1) * BH, h0l + (size_t)(t + 1) * BH,
            nullptr, 512, 1);

    // --- pre1 = y0 @ eW1 ---
    tc_gemm<<<dim3(16, 512), 128, SMEM_BYTES>>>(
        h0h + (size_t)BH, h0l + (size_t)BH, eW1h, eW1l, nullptr, nullptr, nullptr, nullptr,
        nullptr, nullptr, nullptr, pre, 512, 0);

    // --- encoder layer 1 ---
    for (int t = 0; t < TENC; t++)
        tc_gemm<<<gStep, 128, SMEM_BYTES>>>(
            h1h + (size_t)t * BH, h1l + (size_t)t * BH, eU1h, eU1l,
            pre + (size_t)t * Bsz * FOURH, eb1, nullptr, nullptr,
            c1, h1h + (size_t)(t + 1) * BH, h1l + (size_t)(t + 1) * BH,
            nullptr, 512, 1);

    // --- decoder layer 0 (dec_in scalar as rank-1 add in epilogue) ---
    for (int t = 0; t < SEG; t++)
        tc_gemm<<<gStep, 128, SMEM_BYTES>>>(
            h0h + (size_t)(TENC + t) * BH, h0l + (size_t)(TENC + t) * BH, dU0h, dU0l,
            nullptr, db0, decin + t, dW0,
            c0, h0h + (size_t)(TENC + 1 + t) * BH, h0l + (size_t)(TENC + 1 + t) * BH,
            nullptr, 512, 1);

    // --- pre_d1 = d0 @ dW1 ---
    tc_gemm<<<dim3(16, 256), 128, SMEM_BYTES>>>(
        h0h + (size_t)(TENC + 1) * BH, h0l + (size_t)(TENC + 1) * BH, dW1h, dW1l,
        nullptr, nullptr, nullptr, nullptr,
        nullptr, nullptr, nullptr, pre, 512, 0);

    // --- decoder layer 1 ---
    for (int t = 0; t < SEG; t++)
        tc_gemm<<<gStep, 128, SMEM_BYTES>>>(
            h1h + (size_t)(TENC + t) * BH, h1l + (size_t)(TENC + t) * BH, dU1h, dU1l,
            pre + (size_t)t * Bsz * FOURH, db1, nullptr, nullptr,
            c1, h1h + (size_t)(TENC + 1 + t) * BH, h1l + (size_t)(TENC + 1 + t) * BH,
            nullptr, 512, 1);

    // --- final dense ---
    dense_kernel<<<(Bsz * SEG * 32) / 256, 256>>>(h1h, h1l, denseW, denseb, out);
}